// round 4
// baseline (speedup 1.0000x reference)
#include <cuda_runtime.h>
#include <cuda_bf16.h>
#include <cstdint>
#include <math.h>

// Problem constants
#define Bz   16
#define LC   512
#define LQ   64
#define Hd   256
#define ROWS (Bz*LC)     // 8192

// Split-K padded strides (K'' = 3 * K), all in bf16 elements
#define KX   3072        // x'' / W1''  (K=1024)
#define KH   1536        // h1'' / W2'' (K=512)
#define KS   3072        // s1''/e1''/T''/wbt (K=1024, exact now)

// -------------------- device scratch (zero-init .bss) --------------------
__device__ float g_q2[Bz*LQ];
__device__ float g_rowmax[ROWS];
__device__ float g_q2c[Bz*Hd];
__device__ float g_w01[3*1024];
__device__ float g_w10[3*1024];
__device__ float g_w11[3];
__device__ float g_u[48*512];
__device__ float g_v[48*512];
__device__ __align__(16) __nv_bfloat16 g_xs [(size_t)ROWS*KX];
__device__ __align__(16) __nv_bfloat16 g_h1s[(size_t)ROWS*KH];
__device__ __align__(16) __nv_bfloat16 g_s1s[(size_t)ROWS*KS];
__device__ __align__(16) __nv_bfloat16 g_e1s[(size_t)ROWS*KS];
__device__ __align__(16) __nv_bfloat16 g_Ts [(size_t)48*LC*KS];
__device__ __align__(16) __nv_bfloat16 g_w1s[(size_t)512*KX];
__device__ __align__(16) __nv_bfloat16 g_w1e[(size_t)512*KX];
__device__ __align__(16) __nv_bfloat16 g_w2s[(size_t)1024*KH];
__device__ __align__(16) __nv_bfloat16 g_w2e[(size_t)1024*KH];
__device__ __align__(16) __nv_bfloat16 g_wbt[(size_t)3*1024*KS];

// -------------------- helpers --------------------
__device__ __forceinline__ uint32_t smem_u32(const void* p) {
    uint32_t a;
    asm("{ .reg .u64 t; cvta.to.shared.u64 t, %1; cvt.u32.u64 %0, t; }" : "=r"(a) : "l"(p));
    return a;
}
__device__ __forceinline__ void cp16(uint32_t saddr, const void* g) {
    asm volatile("cp.async.ca.shared.global [%0], [%1], 16;" :: "r"(saddr), "l"(g) : "memory");
}
__device__ __forceinline__ void cp_commit() { asm volatile("cp.async.commit_group;" ::: "memory"); }
__device__ __forceinline__ void cp_wait0()  { asm volatile("cp.async.wait_group 0;" ::: "memory"); }

__device__ __forceinline__ void split2(float v, __nv_bfloat16& hi, __nv_bfloat16& lo) {
    hi = __float2bfloat16(v);
    lo = __float2bfloat16(v - __bfloat162float(hi));
}
__device__ __forceinline__ unsigned short b16bits(__nv_bfloat16 h) {
    return *reinterpret_cast<unsigned short*>(&h);
}
__device__ __forceinline__ void ldm4(uint32_t* r, uint32_t saddr) {
    asm volatile("ldmatrix.sync.aligned.m8n8.x4.shared.b16 {%0,%1,%2,%3}, [%4];"
                 : "=r"(r[0]), "=r"(r[1]), "=r"(r[2]), "=r"(r[3]) : "r"(saddr));
}
__device__ __forceinline__ void mma16816(float* c, const uint32_t* a, const uint32_t* b) {
    asm volatile(
        "mma.sync.aligned.m16n8k16.row.col.f32.bf16.bf16.f32 "
        "{%0,%1,%2,%3}, {%4,%5,%6,%7}, {%8,%9}, {%0,%1,%2,%3};"
        : "+f"(c[0]), "+f"(c[1]), "+f"(c[2]), "+f"(c[3])
        : "r"(a[0]), "r"(a[1]), "r"(a[2]), "r"(a[3]), "r"(b[0]), "r"(b[1]));
}

// -------------------- attention front-end --------------------
__device__ __forceinline__ void xsplit_store(__nv_bfloat16* xr, int col, float v) {
    __nv_bfloat16 hi, lo; split2(v, hi, lo);
    xr[col] = hi; xr[col + 1024] = lo; xr[col + 2048] = hi;   // A-layout: hi, lo, hi
}

__global__ void qdot_kernel(const float* __restrict__ ques, const float* __restrict__ wsim,
                            float* __restrict__ q2) {
    int b = blockIdx.x, j = blockIdx.y, l = threadIdx.x;
    const float* q = ques + ((size_t)(b*LQ + j))*Hd;
    float s = 0.f;
    #pragma unroll
    for (int u = 0; u < Hd/32; u++) s += q[l + u*32] * wsim[Hd + l + u*32];
    #pragma unroll
    for (int o = 16; o > 0; o >>= 1) s += __shfl_down_sync(0xffffffffu, s, o);
    if (l == 0) q2[b*LQ + j] = s;
}

__global__ void sim_softmax_c2q_kernel(const float* __restrict__ ctx,
                                       const float* __restrict__ ques,
                                       const float* __restrict__ wsim,
                                       const float* __restrict__ q2,
                                       __nv_bfloat16* __restrict__ xs,
                                       float* __restrict__ rowmax) {
    int row = blockIdx.x, b = row >> 9;
    int t = threadIdx.x, w = t >> 5, l = t & 31;
    __shared__ float ctxs[Hd], cw3[Hd], simv[LQ], sred[8];
    __shared__ float c1s;

    const float* crow = ctx + (size_t)row * Hd;
    float cv = crow[t];
    ctxs[t] = cv;
    cw3[t]  = cv * wsim[2*Hd + t];

    float v = cv * wsim[t];
    #pragma unroll
    for (int o = 16; o > 0; o >>= 1) v += __shfl_down_sync(0xffffffffu, v, o);
    if (l == 0) sred[w] = v;
    __syncthreads();
    if (t == 0) { float s = 0.f; for (int u = 0; u < 8; u++) s += sred[u]; c1s = s; }
    __syncthreads();

    const float* qb = ques + (size_t)b * LQ * Hd;
    #pragma unroll
    for (int jj = 0; jj < 8; jj++) {
        int j = w * 8 + jj;
        const float* q = qb + (size_t)j * Hd;
        float s = 0.f;
        #pragma unroll
        for (int u = 0; u < Hd/32; u++) s += cw3[l + u*32] * q[l + u*32];
        #pragma unroll
        for (int o = 16; o > 0; o >>= 1) s += __shfl_down_sync(0xffffffffu, s, o);
        if (l == 0) simv[j] = c1s + q2[b*LQ + j] + s;
    }
    __syncthreads();

    if (t < 32) {
        float s0 = simv[t], s1v = simv[t + 32];
        float m = fmaxf(s0, s1v);
        #pragma unroll
        for (int o = 16; o > 0; o >>= 1) m = fmaxf(m, __shfl_xor_sync(0xffffffffu, m, o));
        if (t == 0) rowmax[row] = m;
        float e0 = expf(s0 - m), e1v = expf(s1v - m);
        float sum = e0 + e1v;
        #pragma unroll
        for (int o = 16; o > 0; o >>= 1) sum += __shfl_xor_sync(0xffffffffu, sum, o);
        float inv = 1.f / sum;
        simv[t] = e0 * inv; simv[t + 32] = e1v * inv;
    }
    __syncthreads();

    float acc = 0.f;
    #pragma unroll 8
    for (int j = 0; j < LQ; j++) acc += simv[j] * qb[(size_t)j*Hd + t];

    __nv_bfloat16* xr = xs + (size_t)row * KX;
    xsplit_store(xr, t,        ctxs[t]);
    xsplit_store(xr, Hd + t,   acc);
    xsplit_store(xr, 2*Hd + t, ctxs[t] * acc);
}

__global__ void bsoftmax_q2c_kernel(const float* __restrict__ ctx,
                                    const float* __restrict__ rowmax,
                                    float* __restrict__ q2c) {
    int b = blockIdx.x, t = threadIdx.x;
    __shared__ float w[LC]; __shared__ float sred[8]; __shared__ float mshared, sshared;
    w[t] = rowmax[b*LC + t]; w[t + 256] = rowmax[b*LC + t + 256];
    __syncthreads();
    float m = fmaxf(w[t], w[t + 256]);
    #pragma unroll
    for (int o = 16; o > 0; o >>= 1) m = fmaxf(m, __shfl_xor_sync(0xffffffffu, m, o));
    if ((t & 31) == 0) sred[t >> 5] = m;
    __syncthreads();
    if (t == 0) { float mm = sred[0]; for (int u = 1; u < 8; u++) mm = fmaxf(mm, sred[u]); mshared = mm; }
    __syncthreads();
    m = mshared;
    float e0 = expf(w[t] - m), e1v = expf(w[t + 256] - m);
    float s = e0 + e1v;
    #pragma unroll
    for (int o = 16; o > 0; o >>= 1) s += __shfl_xor_sync(0xffffffffu, s, o);
    if ((t & 31) == 0) sred[t >> 5] = s;
    __syncthreads();
    if (t == 0) { float ss = 0.f; for (int u = 0; u < 8; u++) ss += sred[u]; sshared = ss; }
    __syncthreads();
    float inv = 1.f / sshared;
    w[t] = e0 * inv; w[t + 256] = e1v * inv;
    __syncthreads();
    float acc = 0.f;
    const float* cb = ctx + (size_t)b * LC * Hd;
    for (int i = 0; i < LC; i++) acc += w[i] * cb[(size_t)i*Hd + t];
    q2c[b*Hd + t] = acc;
}

__global__ void fillx4_kernel(const float* __restrict__ ctx,
                              const float* __restrict__ q2c,
                              __nv_bfloat16* __restrict__ xs) {
    int row = blockIdx.x, t = threadIdx.x, b = row >> 9;
    float c = ctx[(size_t)row*Hd + t];
    xsplit_store(xs + (size_t)row*KX, 3*Hd + t, c * q2c[b*Hd + t]);
}

// extract rank-1 parts of Wb: w01[c][i]=Wb[i,c,1024], w10[c][j]=Wb[1024,c,j], w11[c]
__global__ void extract_w_kernel(const float* __restrict__ Wb,
                                 float* __restrict__ w01, float* __restrict__ w10,
                                 float* __restrict__ w11) {
    int i = blockIdx.x*256 + threadIdx.x;   // 0..1023
    #pragma unroll
    for (int c = 0; c < 3; c++) {
        w01[c*1024 + i] = Wb[(size_t)i*3075 + c*1025 + 1024];
        w10[c*1024 + i] = Wb[(size_t)1024*3075 + c*1025 + i];
    }
    if (i < 3) w11[i] = Wb[(size_t)1024*3075 + (size_t)i*1025 + 1024];
}

// u[z=b*3+c][x] = start[b,x]·w01[c] + w11[c] ; v[z][y] = end[b,y]·w10[c]
__global__ void uv_kernel(const __nv_bfloat16* __restrict__ s1s,
                          const __nv_bfloat16* __restrict__ e1s,
                          const float* __restrict__ w01, const float* __restrict__ w10,
                          const float* __restrict__ w11,
                          float* __restrict__ u, float* __restrict__ v) {
    int row = blockIdx.x, t = threadIdx.x, w = t >> 5, l = t & 31;
    int b = row >> 9, x = row & 511;
    const __nv_bfloat16* sr = s1s + (size_t)row*KS;
    const __nv_bfloat16* er = e1s + (size_t)row*KS;
    float a[6] = {0,0,0,0,0,0};
    for (int i = t; i < 1024; i += 256) {
        float sv = __bfloat162float(sr[i]) + __bfloat162float(sr[i + 1024]);  // A-layout: hi,lo,hi
        float ev = __bfloat162float(er[i]) + __bfloat162float(er[i + 2048]);  // B-layout: hi,hi,lo
        #pragma unroll
        for (int c = 0; c < 3; c++) {
            a[c]     += sv * w01[c*1024 + i];
            a[3 + c] += ev * w10[c*1024 + i];
        }
    }
    __shared__ float red[6][8];
    #pragma unroll
    for (int q = 0; q < 6; q++) {
        float s = a[q];
        #pragma unroll
        for (int o = 16; o > 0; o >>= 1) s += __shfl_down_sync(0xffffffffu, s, o);
        if (l == 0) red[q][w] = s;
    }
    __syncthreads();
    if (t < 6) {
        float s = 0.f;
        #pragma unroll
        for (int k = 0; k < 8; k++) s += red[t][k];
        if (t < 3) u[(b*3 + t)*512 + x] = s + w11[t];
        else       v[(b*3 + (t - 3))*512 + x] = s;
    }
}

// Transpose + split weights into B-layout [N rows x 3*Kpad]: blocks (hi, hi, lo)
__global__ void prep_bsplit(const float* __restrict__ src, int srcLd,
                            __nv_bfloat16* __restrict__ dst,
                            int Kreal, int Kpad, int Nrows) {
    __shared__ float tile[32][33];
    int k0 = blockIdx.y*32, n0 = blockIdx.x*32;
    int tx = threadIdx.x, ty = threadIdx.y;
    #pragma unroll
    for (int i = 0; i < 32; i += 8) {
        int k = k0 + ty + i, n = n0 + tx;
        tile[ty + i][tx] = (k < Kreal && n < Nrows) ? src[(size_t)k*srcLd + n] : 0.f;
    }
    __syncthreads();
    int ldd = 3*Kpad;
    #pragma unroll
    for (int i = 0; i < 32; i += 8) {
        int n = n0 + ty + i, k = k0 + tx;
        if (n < Nrows) {
            __nv_bfloat16 hi, lo; split2(tile[tx][ty + i], hi, lo);
            size_t base = (size_t)n*ldd + k;
            dst[base] = hi; dst[base + Kpad] = hi; dst[base + 2*Kpad] = lo;
        }
    }
}

// -------------------- warp-mma GEMM (bf16, fp32 acc, ldmatrix) --------------------
// D = A @ B^T ; A [M,K''] K-major, B [N,K''] K-major. All dims exact multiples
// of the 128x128x32 block tile -> no bounds checks. 8 warps, 64x32 warp tile.
#define LDR 40   // smem row stride in bf16 (80 bytes) -> conflict-free

__device__ __forceinline__ void store_pair_split(
    __nv_bfloat16* p, int n, float v0, float v1,
    int blk1, int blk2, int b1lo, const float* bias, int relu)
{
    if (bias) { v0 += bias[n]; v1 += bias[n + 1]; }
    if (relu) { v0 = fmaxf(v0, 0.f); v1 = fmaxf(v1, 0.f); }
    __nv_bfloat16 h0, l0, h1, l1;
    split2(v0, h0, l0); split2(v1, h1, l1);
    uint32_t H = (uint32_t)b16bits(h0) | ((uint32_t)b16bits(h1) << 16);
    uint32_t L = (uint32_t)b16bits(l0) | ((uint32_t)b16bits(l1) << 16);
    *reinterpret_cast<uint32_t*>(p + n) = H;
    *reinterpret_cast<uint32_t*>(p + blk1 + n) = b1lo ? L : H;
    *reinterpret_cast<uint32_t*>(p + blk2 + n) = b1lo ? H : L;
}

__global__ __launch_bounds__(256, 2)
void mma_gemm(const __nv_bfloat16* __restrict__ A, int lda, long long aZb, long long aZc,
              const __nv_bfloat16* __restrict__ B, int ldb, long long bZb, long long bZc,
              int nch, int zdiv, int mode,
              __nv_bfloat16* outS, int ldo, int blk1, int blk2, int b1lo,
              const float* bias, int relu,
              float* outF, int ldcM, long long cZb, long long cZc,
              const float* uArr, const float* vArr)
{
    __shared__ __align__(16) __nv_bfloat16 sA[2][128*LDR];
    __shared__ __align__(16) __nv_bfloat16 sB[2][128*LDR];

    const int LDR2 = LDR*2;
    int tid = threadIdx.x;
    int z = blockIdx.z, zb = z / zdiv, zc = z - zb * zdiv;
    const __nv_bfloat16* Ab = A + (size_t)zb*aZb + (size_t)zc*aZc + (size_t)(blockIdx.y*128)*lda;
    const __nv_bfloat16* Bb = B + (size_t)zb*bZb + (size_t)zc*bZc + (size_t)(blockIdx.x*128)*ldb;
    int m0 = blockIdx.y * 128, n0 = blockIdx.x * 128;

    int lane = tid & 31, wid = tid >> 5;
    int wm = (wid & 1) * 64, wn = (wid >> 1) * 32;
    int ar = lane >> 2, ac = (lane & 3) * 2;

    int lrow = tid >> 2, lseg = tid & 3;               // loader: 4 threads/row
    uint32_t sA0 = smem_u32(&sA[0][0]), sB0 = smem_u32(&sB[0][0]);
    uint32_t sA1 = smem_u32(&sA[1][0]), sB1 = smem_u32(&sB[1][0]);

    // ldmatrix per-thread offsets
    uint32_t aoff = (uint32_t)(wm + (lane & 15))*LDR2 + (lane >> 4)*16;
    uint32_t boff = (uint32_t)(wn + (lane & 7))*LDR2 + (lane >> 3)*16;

    float acc[4][4][4];
    #pragma unroll
    for (int i = 0; i < 4; i++)
        #pragma unroll
        for (int j = 0; j < 4; j++)
            #pragma unroll
            for (int q = 0; q < 4; q++) acc[i][j][q] = 0.f;

    // prologue: load chunk 0 into buf 0
    {
        const __nv_bfloat16* ga = Ab + (size_t)lrow*lda + lseg*8;
        const __nv_bfloat16* gb = Bb + (size_t)lrow*ldb + lseg*8;
        uint32_t so = lrow*LDR2 + lseg*16;
        cp16(sA0 + so, ga);            cp16(sB0 + so, gb);
        cp16(sA0 + so + 64*LDR2, ga + (size_t)64*lda);
        cp16(sB0 + so + 64*LDR2, gb + (size_t)64*ldb);
        cp_commit();
    }

    for (int c = 0; c < nch; c++) {
        cp_wait0();
        __syncthreads();
        int buf = c & 1;
        if (c + 1 < nch) {
            int k0 = (c + 1) * 32;
            const __nv_bfloat16* ga = Ab + (size_t)lrow*lda + k0 + lseg*8;
            const __nv_bfloat16* gb = Bb + (size_t)lrow*ldb + k0 + lseg*8;
            uint32_t da = (buf ? sA0 : sA1), db = (buf ? sB0 : sB1);
            uint32_t so = lrow*LDR2 + lseg*16;
            cp16(da + so, ga);            cp16(db + so, gb);
            cp16(da + so + 64*LDR2, ga + (size_t)64*lda);
            cp16(db + so + 64*LDR2, gb + (size_t)64*ldb);
            cp_commit();
        }
        uint32_t sa = buf ? sA1 : sA0;
        uint32_t sbb = buf ? sB1 : sB0;

        uint32_t bf[4][4];
        #pragma unroll
        for (int nt = 0; nt < 4; nt++) ldm4(bf[nt], sbb + boff + nt*(8*LDR2));
        #pragma unroll
        for (int ks = 0; ks < 2; ks++) {
            #pragma unroll
            for (int mt = 0; mt < 4; mt++) {
                uint32_t af[4];
                ldm4(af, sa + aoff + mt*(16*LDR2) + ks*32);
                #pragma unroll
                for (int nt = 0; nt < 4; nt++)
                    mma16816(acc[mt][nt], af, &bf[nt][ks*2]);
            }
        }
        __syncthreads();
    }

    // -------- epilogue --------
    if (mode == 0) {
        __nv_bfloat16* base = outS + (size_t)zb*cZb + (size_t)zc*cZc;
        #pragma unroll
        for (int mt = 0; mt < 4; mt++) {
            int m = m0 + wm + mt*16 + ar;
            __nv_bfloat16* p0 = base + (size_t)m*ldo;
            __nv_bfloat16* p1 = p0 + (size_t)8*ldo;
            #pragma unroll
            for (int nt = 0; nt < 4; nt++) {
                int n = n0 + wn + nt*8 + ac;
                store_pair_split(p0, n, acc[mt][nt][0], acc[mt][nt][1], blk1, blk2, b1lo, bias, relu);
                store_pair_split(p1, n, acc[mt][nt][2], acc[mt][nt][3], blk1, blk2, b1lo, bias, relu);
            }
        }
    } else {
        float* base = outF + (size_t)zb*cZb + (size_t)zc*cZc;
        const float* uz = uArr + (size_t)z*512;
        const float* vz = vArr + (size_t)z*512;
        #pragma unroll
        for (int mt = 0; mt < 4; mt++) {
            int m = m0 + wm + mt*16 + ar;
            float u0 = uz[m], u1 = uz[m + 8];
            float* p0 = base + (size_t)m*ldcM;
            float* p1 = p0 + (size_t)8*ldcM;
            #pragma unroll
            for (int nt = 0; nt < 4; nt++) {
                int n = n0 + wn + nt*8 + ac;
                float vn0 = vz[n], vn1 = vz[n + 1];
                p0[(size_t)n*3]     = acc[mt][nt][0] + u0 + vn0;
                p0[(size_t)(n+1)*3] = acc[mt][nt][1] + u0 + vn1;
                p1[(size_t)n*3]     = acc[mt][nt][2] + u1 + vn0;
                p1[(size_t)(n+1)*3] = acc[mt][nt][3] + u1 + vn1;
            }
        }
    }
}

// -------------------- launcher --------------------
extern "C" void kernel_launch(void* const* d_in, const int* in_sizes, int n_in,
                              void* d_out, int out_size) {
    const float* ctx  = (const float*)d_in[0];
    const float* ques = (const float*)d_in[1];
    const float* wsim = (const float*)d_in[2];
    const float* W1s  = (const float*)d_in[3];
    const float* b1s  = (const float*)d_in[4];
    const float* W2s  = (const float*)d_in[5];
    const float* b2s  = (const float*)d_in[6];
    const float* W1e  = (const float*)d_in[7];
    const float* b1e  = (const float*)d_in[8];
    const float* W2e  = (const float*)d_in[9];
    const float* b2e  = (const float*)d_in[10];
    const float* Wb   = (const float*)d_in[11];
    float* out = (float*)d_out;

    float *q2, *rowmax, *q2c, *w01, *w10, *w11, *u, *v;
    __nv_bfloat16 *xs, *h1s, *s1s, *e1s, *Ts, *w1s, *w1e, *w2s, *w2e, *wbt;
    cudaGetSymbolAddress((void**)&q2, g_q2);
    cudaGetSymbolAddress((void**)&rowmax, g_rowmax);
    cudaGetSymbolAddress((void**)&q2c, g_q2c);
    cudaGetSymbolAddress((void**)&w01, g_w01);
    cudaGetSymbolAddress((void**)&w10, g_w10);
    cudaGetSymbolAddress((void**)&w11, g_w11);
    cudaGetSymbolAddress((void**)&u, g_u);
    cudaGetSymbolAddress((void**)&v, g_v);
    cudaGetSymbolAddress((void**)&xs, g_xs);
    cudaGetSymbolAddress((void**)&h1s, g_h1s);
    cudaGetSymbolAddress((void**)&s1s, g_s1s);
    cudaGetSymbolAddress((void**)&e1s, g_e1s);
    cudaGetSymbolAddress((void**)&Ts, g_Ts);
    cudaGetSymbolAddress((void**)&w1s, g_w1s);
    cudaGetSymbolAddress((void**)&w1e, g_w1e);
    cudaGetSymbolAddress((void**)&w2s, g_w2s);
    cudaGetSymbolAddress((void**)&w2e, g_w2e);
    cudaGetSymbolAddress((void**)&wbt, g_wbt);

    // front-end
    qdot_kernel<<<dim3(Bz, LQ), 32>>>(ques, wsim, q2);
    sim_softmax_c2q_kernel<<<ROWS, 256>>>(ctx, ques, wsim, q2, xs, rowmax);
    bsoftmax_q2c_kernel<<<Bz, 256>>>(ctx, rowmax, q2c);
    fillx4_kernel<<<ROWS, 256>>>(ctx, q2c, xs);
    extract_w_kernel<<<4, 256>>>(Wb, w01, w10, w11);

    // weight prep (transpose + hi/lo split, B-layout hi,hi,lo)
    prep_bsplit<<<dim3(16, 32), dim3(32, 8)>>>(W1s, 512, w1s, 1024, 1024, 512);
    prep_bsplit<<<dim3(16, 32), dim3(32, 8)>>>(W1e, 512, w1e, 1024, 1024, 512);
    prep_bsplit<<<dim3(32, 16), dim3(32, 8)>>>(W2s, 1024, w2s, 512, 512, 1024);
    prep_bsplit<<<dim3(32, 16), dim3(32, 8)>>>(W2e, 1024, w2e, 512, 512, 1024);
    for (int c = 0; c < 3; c++)
        prep_bsplit<<<dim3(32, 32), dim3(32, 8)>>>(Wb + (size_t)c*1025, 3075,
                                                   wbt + (size_t)c*1024*KS, 1024, 1024, 1024);

    long long zero = 0;
    // FFW start: h1 = relu(x@W1s + b1s)  (A-layout out: hi,lo,hi)
    mma_gemm<<<dim3(4, 64, 1), 256>>>(xs, KX, zero, zero, w1s, KX, zero, zero,
        96, 1, 0, h1s, KH, 512, 1024, 1, b1s, 1, nullptr, 0, zero, zero, nullptr, nullptr);
    // start = h1@W2s + b2s  (A-layout hi,lo,hi)
    mma_gemm<<<dim3(8, 64, 1), 256>>>(h1s, KH, zero, zero, w2s, KH, zero, zero,
        48, 1, 0, s1s, KS, 1024, 2048, 1, b2s, 0, nullptr, 0, zero, zero, nullptr, nullptr);
    // FFW end
    mma_gemm<<<dim3(4, 64, 1), 256>>>(xs, KX, zero, zero, w1e, KX, zero, zero,
        96, 1, 0, h1s, KH, 512, 1024, 1, b1e, 1, nullptr, 0, zero, zero, nullptr, nullptr);
    // end = h1@W2e + b2e  (B-layout hi,hi,lo)
    mma_gemm<<<dim3(8, 64, 1), 256>>>(h1s, KH, zero, zero, w2e, KH, zero, zero,
        48, 1, 0, e1s, KS, 1024, 2048, 0, b2e, 0, nullptr, 0, zero, zero, nullptr, nullptr);

    // rank-1 terms
    uv_kernel<<<ROWS, 256>>>(s1s, e1s, w01, w10, w11, u, v);

    // Biaffine stage 1: T[z=b*3+c] = start_b @ wbt_c^T  (A-layout out)
    mma_gemm<<<dim3(8, 4, 48), 256>>>(
        s1s, KS, (long long)LC*KS, zero,
        wbt, KS, zero, (long long)1024*KS,
        96, 3,
        0, Ts, KS, 1024, 2048, 1, nullptr, 0,
        nullptr, 0, (long long)3*LC*KS, (long long)LC*KS, nullptr, nullptr);

    // Biaffine stage 2: out[b,:,:,c] = T[z] @ end_b^T + u[z][x] + v[z][y]
    mma_gemm<<<dim3(4, 4, 48), 256>>>(
        Ts, KS, (long long)3*LC*KS, (long long)LC*KS,
        e1s, KS, (long long)LC*KS, zero,
        96, 3,
        1, nullptr, 0, 0, 0, 0, nullptr, 0,
        out, LC*3, (long long)LC*LC*3, 1ll, u, v);
}

// round 5
// speedup vs baseline: 1.3306x; 1.3306x over previous
#include <cuda_runtime.h>
#include <cuda_bf16.h>
#include <cstdint>
#include <math.h>

// Problem constants
#define Bz   16
#define LC   512
#define LQ   64
#define Hd   256
#define ROWS (Bz*LC)     // 8192

// Split-K padded strides (K'' = 3 * K), all in bf16 elements
#define KX   3072        // x'' / W1''  (K=1024)
#define KH   1536        // h1'' / W2'' (K=512)
#define KS   3072        // s1''/e1''/T''/wbt (K=1024, exact)

// -------------------- device scratch (zero-init .bss) --------------------
__device__ float g_q2[Bz*LQ];
__device__ float g_rowmax[ROWS];
__device__ float g_q2c[Bz*Hd];
__device__ float g_w01[3*1024];
__device__ float g_w10[3*1024];
__device__ float g_w11[3];
__device__ float g_u[48*512];
__device__ float g_v[48*512];
__device__ __align__(16) __nv_bfloat16 g_xs [(size_t)ROWS*KX];
__device__ __align__(16) __nv_bfloat16 g_h1s[(size_t)ROWS*KH];
__device__ __align__(16) __nv_bfloat16 g_s1s[(size_t)ROWS*KS];
__device__ __align__(16) __nv_bfloat16 g_e1s[(size_t)ROWS*KS];
__device__ __align__(16) __nv_bfloat16 g_Ts [(size_t)48*LC*KS];
__device__ __align__(16) __nv_bfloat16 g_w1s[(size_t)512*KX];
__device__ __align__(16) __nv_bfloat16 g_w1e[(size_t)512*KX];
__device__ __align__(16) __nv_bfloat16 g_w2s[(size_t)1024*KH];
__device__ __align__(16) __nv_bfloat16 g_w2e[(size_t)1024*KH];
__device__ __align__(16) __nv_bfloat16 g_wbt[(size_t)3*1024*KS];

// -------------------- helpers --------------------
__device__ __forceinline__ uint32_t smem_u32(const void* p) {
    uint32_t a;
    asm("{ .reg .u64 t; cvta.to.shared.u64 t, %1; cvt.u32.u64 %0, t; }" : "=r"(a) : "l"(p));
    return a;
}
__device__ __forceinline__ void cp16(uint32_t saddr, const void* g) {
    asm volatile("cp.async.ca.shared.global [%0], [%1], 16;" :: "r"(saddr), "l"(g) : "memory");
}
__device__ __forceinline__ void cp_commit() { asm volatile("cp.async.commit_group;" ::: "memory"); }
__device__ __forceinline__ void cp_wait0()  { asm volatile("cp.async.wait_group 0;" ::: "memory"); }

__device__ __forceinline__ void split2(float v, __nv_bfloat16& hi, __nv_bfloat16& lo) {
    hi = __float2bfloat16(v);
    lo = __float2bfloat16(v - __bfloat162float(hi));
}
__device__ __forceinline__ unsigned short b16bits(__nv_bfloat16 h) {
    return *reinterpret_cast<unsigned short*>(&h);
}
__device__ __forceinline__ void mma16816(float* c, const uint32_t* a, const uint32_t* b) {
    asm volatile(
        "mma.sync.aligned.m16n8k16.row.col.f32.bf16.bf16.f32 "
        "{%0,%1,%2,%3}, {%4,%5,%6,%7}, {%8,%9}, {%0,%1,%2,%3};"
        : "+f"(c[0]), "+f"(c[1]), "+f"(c[2]), "+f"(c[3])
        : "r"(a[0]), "r"(a[1]), "r"(a[2]), "r"(a[3]), "r"(b[0]), "r"(b[1]));
}

// -------------------- attention front-end --------------------
__device__ __forceinline__ void xsplit_store(__nv_bfloat16* xr, int col, float v) {
    __nv_bfloat16 hi, lo; split2(v, hi, lo);
    xr[col] = hi; xr[col + 1024] = lo; xr[col + 2048] = hi;   // A-layout: hi, lo, hi
}

__global__ void qdot_kernel(const float* __restrict__ ques, const float* __restrict__ wsim,
                            float* __restrict__ q2) {
    int b = blockIdx.x, j = blockIdx.y, l = threadIdx.x;
    const float* q = ques + ((size_t)(b*LQ + j))*Hd;
    float s = 0.f;
    #pragma unroll
    for (int u = 0; u < Hd/32; u++) s += q[l + u*32] * wsim[Hd + l + u*32];
    #pragma unroll
    for (int o = 16; o > 0; o >>= 1) s += __shfl_down_sync(0xffffffffu, s, o);
    if (l == 0) q2[b*LQ + j] = s;
}

__global__ void sim_softmax_c2q_kernel(const float* __restrict__ ctx,
                                       const float* __restrict__ ques,
                                       const float* __restrict__ wsim,
                                       const float* __restrict__ q2,
                                       __nv_bfloat16* __restrict__ xs,
                                       float* __restrict__ rowmax) {
    int row = blockIdx.x, b = row >> 9;
    int t = threadIdx.x, w = t >> 5, l = t & 31;
    __shared__ float ctxs[Hd], cw3[Hd], simv[LQ], sred[8];
    __shared__ float c1s;

    const float* crow = ctx + (size_t)row * Hd;
    float cv = crow[t];
    ctxs[t] = cv;
    cw3[t]  = cv * wsim[2*Hd + t];

    float v = cv * wsim[t];
    #pragma unroll
    for (int o = 16; o > 0; o >>= 1) v += __shfl_down_sync(0xffffffffu, v, o);
    if (l == 0) sred[w] = v;
    __syncthreads();
    if (t == 0) { float s = 0.f; for (int u = 0; u < 8; u++) s += sred[u]; c1s = s; }
    __syncthreads();

    const float* qb = ques + (size_t)b * LQ * Hd;
    #pragma unroll
    for (int jj = 0; jj < 8; jj++) {
        int j = w * 8 + jj;
        const float* q = qb + (size_t)j * Hd;
        float s = 0.f;
        #pragma unroll
        for (int u = 0; u < Hd/32; u++) s += cw3[l + u*32] * q[l + u*32];
        #pragma unroll
        for (int o = 16; o > 0; o >>= 1) s += __shfl_down_sync(0xffffffffu, s, o);
        if (l == 0) simv[j] = c1s + q2[b*LQ + j] + s;
    }
    __syncthreads();

    if (t < 32) {
        float s0 = simv[t], s1v = simv[t + 32];
        float m = fmaxf(s0, s1v);
        #pragma unroll
        for (int o = 16; o > 0; o >>= 1) m = fmaxf(m, __shfl_xor_sync(0xffffffffu, m, o));
        if (t == 0) rowmax[row] = m;
        float e0 = expf(s0 - m), e1v = expf(s1v - m);
        float sum = e0 + e1v;
        #pragma unroll
        for (int o = 16; o > 0; o >>= 1) sum += __shfl_xor_sync(0xffffffffu, sum, o);
        float inv = 1.f / sum;
        simv[t] = e0 * inv; simv[t + 32] = e1v * inv;
    }
    __syncthreads();

    float acc = 0.f;
    #pragma unroll 8
    for (int j = 0; j < LQ; j++) acc += simv[j] * qb[(size_t)j*Hd + t];

    __nv_bfloat16* xr = xs + (size_t)row * KX;
    xsplit_store(xr, t,        ctxs[t]);
    xsplit_store(xr, Hd + t,   acc);
    xsplit_store(xr, 2*Hd + t, ctxs[t] * acc);
}

__global__ void bsoftmax_q2c_kernel(const float* __restrict__ ctx,
                                    const float* __restrict__ rowmax,
                                    float* __restrict__ q2c) {
    int b = blockIdx.x, t = threadIdx.x;
    __shared__ float w[LC]; __shared__ float sred[8]; __shared__ float mshared, sshared;
    w[t] = rowmax[b*LC + t]; w[t + 256] = rowmax[b*LC + t + 256];
    __syncthreads();
    float m = fmaxf(w[t], w[t + 256]);
    #pragma unroll
    for (int o = 16; o > 0; o >>= 1) m = fmaxf(m, __shfl_xor_sync(0xffffffffu, m, o));
    if ((t & 31) == 0) sred[t >> 5] = m;
    __syncthreads();
    if (t == 0) { float mm = sred[0]; for (int u = 1; u < 8; u++) mm = fmaxf(mm, sred[u]); mshared = mm; }
    __syncthreads();
    m = mshared;
    float e0 = expf(w[t] - m), e1v = expf(w[t + 256] - m);
    float s = e0 + e1v;
    #pragma unroll
    for (int o = 16; o > 0; o >>= 1) s += __shfl_xor_sync(0xffffffffu, s, o);
    if ((t & 31) == 0) sred[t >> 5] = s;
    __syncthreads();
    if (t == 0) { float ss = 0.f; for (int u = 0; u < 8; u++) ss += sred[u]; sshared = ss; }
    __syncthreads();
    float inv = 1.f / sshared;
    w[t] = e0 * inv; w[t + 256] = e1v * inv;
    __syncthreads();
    float acc = 0.f;
    const float* cb = ctx + (size_t)b * LC * Hd;
    for (int i = 0; i < LC; i++) acc += w[i] * cb[(size_t)i*Hd + t];
    q2c[b*Hd + t] = acc;
}

__global__ void fillx4_kernel(const float* __restrict__ ctx,
                              const float* __restrict__ q2c,
                              __nv_bfloat16* __restrict__ xs) {
    int row = blockIdx.x, t = threadIdx.x, b = row >> 9;
    float c = ctx[(size_t)row*Hd + t];
    xsplit_store(xs + (size_t)row*KX, 3*Hd + t, c * q2c[b*Hd + t]);
}

// extract rank-1 parts of Wb: w01[c][i]=Wb[i,c,1024], w10[c][j]=Wb[1024,c,j], w11[c]
__global__ void extract_w_kernel(const float* __restrict__ Wb,
                                 float* __restrict__ w01, float* __restrict__ w10,
                                 float* __restrict__ w11) {
    int i = blockIdx.x*256 + threadIdx.x;   // 0..1023
    #pragma unroll
    for (int c = 0; c < 3; c++) {
        w01[c*1024 + i] = Wb[(size_t)i*3075 + c*1025 + 1024];
        w10[c*1024 + i] = Wb[(size_t)1024*3075 + c*1025 + i];
    }
    if (i < 3) w11[i] = Wb[(size_t)1024*3075 + (size_t)i*1025 + 1024];
}

// u[z=b*3+c][x] = start[b,x]·w01[c] + w11[c] ; v[z][y] = end[b,y]·w10[c]
__global__ void uv_kernel(const __nv_bfloat16* __restrict__ s1s,
                          const __nv_bfloat16* __restrict__ e1s,
                          const float* __restrict__ w01, const float* __restrict__ w10,
                          const float* __restrict__ w11,
                          float* __restrict__ u, float* __restrict__ v) {
    int row = blockIdx.x, t = threadIdx.x, w = t >> 5, l = t & 31;
    int b = row >> 9, x = row & 511;
    const __nv_bfloat16* sr = s1s + (size_t)row*KS;
    const __nv_bfloat16* er = e1s + (size_t)row*KS;
    float a[6] = {0,0,0,0,0,0};
    for (int i = t; i < 1024; i += 256) {
        float sv = __bfloat162float(sr[i]) + __bfloat162float(sr[i + 1024]);  // A-layout: hi,lo,hi
        float ev = __bfloat162float(er[i]) + __bfloat162float(er[i + 2048]);  // B-layout: hi,hi,lo
        #pragma unroll
        for (int c = 0; c < 3; c++) {
            a[c]     += sv * w01[c*1024 + i];
            a[3 + c] += ev * w10[c*1024 + i];
        }
    }
    __shared__ float red[6][8];
    #pragma unroll
    for (int q = 0; q < 6; q++) {
        float s = a[q];
        #pragma unroll
        for (int o = 16; o > 0; o >>= 1) s += __shfl_down_sync(0xffffffffu, s, o);
        if (l == 0) red[q][w] = s;
    }
    __syncthreads();
    if (t < 6) {
        float s = 0.f;
        #pragma unroll
        for (int k = 0; k < 8; k++) s += red[t][k];
        if (t < 3) u[(b*3 + t)*512 + x] = s + w11[t];
        else       v[(b*3 + (t - 3))*512 + x] = s;
    }
}

// Transpose + split weights into B-layout [N rows x 3*Kpad]: blocks (hi, hi, lo)
__global__ void prep_bsplit(const float* __restrict__ src, int srcLd,
                            __nv_bfloat16* __restrict__ dst,
                            int Kreal, int Kpad, int Nrows) {
    __shared__ float tile[32][33];
    int k0 = blockIdx.y*32, n0 = blockIdx.x*32;
    int tx = threadIdx.x, ty = threadIdx.y;
    #pragma unroll
    for (int i = 0; i < 32; i += 8) {
        int k = k0 + ty + i, n = n0 + tx;
        tile[ty + i][tx] = (k < Kreal && n < Nrows) ? src[(size_t)k*srcLd + n] : 0.f;
    }
    __syncthreads();
    int ldd = 3*Kpad;
    #pragma unroll
    for (int i = 0; i < 32; i += 8) {
        int n = n0 + ty + i, k = k0 + tx;
        if (n < Nrows) {
            __nv_bfloat16 hi, lo; split2(tile[tx][ty + i], hi, lo);
            size_t base = (size_t)n*ldd + k;
            dst[base] = hi; dst[base + Kpad] = hi; dst[base + 2*Kpad] = lo;
        }
    }
}

// -------------------- warp-mma GEMM (bf16, fp32 acc) --------------------
// D = A @ B^T ; A [M,K''] K-major, B [N,K''] K-major. All dims exact multiples
// of the 128x128x32 block tile -> no bounds checks. 8 warps, 64x32 warp tile.
// Round-3 scheduling: all fragments loaded up-front per k-step (scalar LDS).
#define LDR 40   // smem row stride in bf16 (80 bytes) -> conflict-free

__device__ __forceinline__ void store_pair_split(
    __nv_bfloat16* p, int n, float v0, float v1,
    int blk1, int blk2, int b1lo, const float* bias, int relu)
{
    if (bias) { v0 += bias[n]; v1 += bias[n + 1]; }
    if (relu) { v0 = fmaxf(v0, 0.f); v1 = fmaxf(v1, 0.f); }
    __nv_bfloat16 h0, l0, h1, l1;
    split2(v0, h0, l0); split2(v1, h1, l1);
    uint32_t H = (uint32_t)b16bits(h0) | ((uint32_t)b16bits(h1) << 16);
    uint32_t L = (uint32_t)b16bits(l0) | ((uint32_t)b16bits(l1) << 16);
    *reinterpret_cast<uint32_t*>(p + n) = H;
    *reinterpret_cast<uint32_t*>(p + blk1 + n) = b1lo ? L : H;
    *reinterpret_cast<uint32_t*>(p + blk2 + n) = b1lo ? H : L;
}

__global__ __launch_bounds__(256, 2)
void mma_gemm(const __nv_bfloat16* __restrict__ A, int lda, long long aZb, long long aZc,
              const __nv_bfloat16* __restrict__ B, int ldb, long long bZb, long long bZc,
              int nch, int zdiv, int mode,
              __nv_bfloat16* outS, int ldo, int blk1, int blk2, int b1lo,
              const float* bias, int relu,
              float* outF, int ldcM, long long cZb, long long cZc,
              const float* uArr, const float* vArr)
{
    __shared__ __align__(16) __nv_bfloat16 sA[2][128*LDR];
    __shared__ __align__(16) __nv_bfloat16 sB[2][128*LDR];

    const int LDR2 = LDR*2;
    int tid = threadIdx.x;
    int z = blockIdx.z, zb = z / zdiv, zc = z - zb * zdiv;
    const __nv_bfloat16* Ab = A + (size_t)zb*aZb + (size_t)zc*aZc + (size_t)(blockIdx.y*128)*lda;
    const __nv_bfloat16* Bb = B + (size_t)zb*bZb + (size_t)zc*bZc + (size_t)(blockIdx.x*128)*ldb;
    int m0 = blockIdx.y * 128, n0 = blockIdx.x * 128;

    int lane = tid & 31, wid = tid >> 5;
    int wm = (wid & 1) * 64, wn = (wid >> 1) * 32;
    int ar = lane >> 2, ac = (lane & 3) * 2;

    int lrow = tid >> 2, lseg = tid & 3;               // loader: 4 threads/row
    uint32_t sA0 = smem_u32(&sA[0][0]), sB0 = smem_u32(&sB[0][0]);
    uint32_t sA1 = smem_u32(&sA[1][0]), sB1 = smem_u32(&sB[1][0]);

    float acc[4][4][4];
    #pragma unroll
    for (int i = 0; i < 4; i++)
        #pragma unroll
        for (int j = 0; j < 4; j++)
            #pragma unroll
            for (int q = 0; q < 4; q++) acc[i][j][q] = 0.f;

    // prologue: load chunk 0 into buf 0
    {
        const __nv_bfloat16* ga = Ab + (size_t)lrow*lda + lseg*8;
        const __nv_bfloat16* gb = Bb + (size_t)lrow*ldb + lseg*8;
        uint32_t so = lrow*LDR2 + lseg*16;
        cp16(sA0 + so, ga);            cp16(sB0 + so, gb);
        cp16(sA0 + so + 64*LDR2, ga + (size_t)64*lda);
        cp16(sB0 + so + 64*LDR2, gb + (size_t)64*ldb);
        cp_commit();
    }

    for (int c = 0; c < nch; c++) {
        cp_wait0();
        __syncthreads();
        int buf = c & 1;
        if (c + 1 < nch) {
            int k0 = (c + 1) * 32;
            const __nv_bfloat16* ga = Ab + (size_t)lrow*lda + k0 + lseg*8;
            const __nv_bfloat16* gb = Bb + (size_t)lrow*ldb + k0 + lseg*8;
            uint32_t da = (buf ? sA0 : sA1), db = (buf ? sB0 : sB1);
            uint32_t so = lrow*LDR2 + lseg*16;
            cp16(da + so, ga);            cp16(db + so, gb);
            cp16(da + so + 64*LDR2, ga + (size_t)64*lda);
            cp16(db + so + 64*LDR2, gb + (size_t)64*ldb);
            cp_commit();
        }
        const __nv_bfloat16* As = &sA[buf][0];
        const __nv_bfloat16* Bs = &sB[buf][0];
        #pragma unroll
        for (int ks = 0; ks < 2; ks++) {
            int kc = ks * 16;
            uint32_t af[4][4], bf[4][2];
            #pragma unroll
            for (int mt = 0; mt < 4; mt++) {
                int r0 = wm + mt*16 + ar;
                af[mt][0] = *reinterpret_cast<const uint32_t*>(As + r0*LDR + kc + ac);
                af[mt][1] = *reinterpret_cast<const uint32_t*>(As + (r0+8)*LDR + kc + ac);
                af[mt][2] = *reinterpret_cast<const uint32_t*>(As + r0*LDR + kc + ac + 8);
                af[mt][3] = *reinterpret_cast<const uint32_t*>(As + (r0+8)*LDR + kc + ac + 8);
            }
            #pragma unroll
            for (int nt = 0; nt < 4; nt++) {
                int nr = wn + nt*8 + ar;
                bf[nt][0] = *reinterpret_cast<const uint32_t*>(Bs + nr*LDR + kc + ac);
                bf[nt][1] = *reinterpret_cast<const uint32_t*>(Bs + nr*LDR + kc + ac + 8);
            }
            #pragma unroll
            for (int mt = 0; mt < 4; mt++)
                #pragma unroll
                for (int nt = 0; nt < 4; nt++)
                    mma16816(acc[mt][nt], af[mt], bf[nt]);
        }
        __syncthreads();
    }

    // -------- epilogue --------
    if (mode == 0) {
        __nv_bfloat16* base = outS + (size_t)zb*cZb + (size_t)zc*cZc;
        #pragma unroll
        for (int mt = 0; mt < 4; mt++) {
            int m = m0 + wm + mt*16 + ar;
            __nv_bfloat16* p0 = base + (size_t)m*ldo;
            __nv_bfloat16* p1 = p0 + (size_t)8*ldo;
            #pragma unroll
            for (int nt = 0; nt < 4; nt++) {
                int n = n0 + wn + nt*8 + ac;
                store_pair_split(p0, n, acc[mt][nt][0], acc[mt][nt][1], blk1, blk2, b1lo, bias, relu);
                store_pair_split(p1, n, acc[mt][nt][2], acc[mt][nt][3], blk1, blk2, b1lo, bias, relu);
            }
        }
    } else {
        float* base = outF + (size_t)zb*cZb + (size_t)zc*cZc;
        const float* uz = uArr + (size_t)z*512;
        const float* vz = vArr + (size_t)z*512;
        #pragma unroll
        for (int mt = 0; mt < 4; mt++) {
            int m = m0 + wm + mt*16 + ar;
            float u0 = uz[m], u1 = uz[m + 8];
            float* p0 = base + (size_t)m*ldcM;
            float* p1 = p0 + (size_t)8*ldcM;
            #pragma unroll
            for (int nt = 0; nt < 4; nt++) {
                int n = n0 + wn + nt*8 + ac;
                float vn0 = vz[n], vn1 = vz[n + 1];
                p0[(size_t)n*3]     = acc[mt][nt][0] + u0 + vn0;
                p0[(size_t)(n+1)*3] = acc[mt][nt][1] + u0 + vn1;
                p1[(size_t)n*3]     = acc[mt][nt][2] + u1 + vn0;
                p1[(size_t)(n+1)*3] = acc[mt][nt][3] + u1 + vn1;
            }
        }
    }
}

// -------------------- launcher --------------------
extern "C" void kernel_launch(void* const* d_in, const int* in_sizes, int n_in,
                              void* d_out, int out_size) {
    const float* ctx  = (const float*)d_in[0];
    const float* ques = (const float*)d_in[1];
    const float* wsim = (const float*)d_in[2];
    const float* W1s  = (const float*)d_in[3];
    const float* b1s  = (const float*)d_in[4];
    const float* W2s  = (const float*)d_in[5];
    const float* b2s  = (const float*)d_in[6];
    const float* W1e  = (const float*)d_in[7];
    const float* b1e  = (const float*)d_in[8];
    const float* W2e  = (const float*)d_in[9];
    const float* b2e  = (const float*)d_in[10];
    const float* Wb   = (const float*)d_in[11];
    float* out = (float*)d_out;

    float *q2, *rowmax, *q2c, *w01, *w10, *w11, *u, *v;
    __nv_bfloat16 *xs, *h1s, *s1s, *e1s, *Ts, *w1s, *w1e, *w2s, *w2e, *wbt;
    cudaGetSymbolAddress((void**)&q2, g_q2);
    cudaGetSymbolAddress((void**)&rowmax, g_rowmax);
    cudaGetSymbolAddress((void**)&q2c, g_q2c);
    cudaGetSymbolAddress((void**)&w01, g_w01);
    cudaGetSymbolAddress((void**)&w10, g_w10);
    cudaGetSymbolAddress((void**)&w11, g_w11);
    cudaGetSymbolAddress((void**)&u, g_u);
    cudaGetSymbolAddress((void**)&v, g_v);
    cudaGetSymbolAddress((void**)&xs, g_xs);
    cudaGetSymbolAddress((void**)&h1s, g_h1s);
    cudaGetSymbolAddress((void**)&s1s, g_s1s);
    cudaGetSymbolAddress((void**)&e1s, g_e1s);
    cudaGetSymbolAddress((void**)&Ts, g_Ts);
    cudaGetSymbolAddress((void**)&w1s, g_w1s);
    cudaGetSymbolAddress((void**)&w1e, g_w1e);
    cudaGetSymbolAddress((void**)&w2s, g_w2s);
    cudaGetSymbolAddress((void**)&w2e, g_w2e);
    cudaGetSymbolAddress((void**)&wbt, g_wbt);

    // front-end
    qdot_kernel<<<dim3(Bz, LQ), 32>>>(ques, wsim, q2);
    sim_softmax_c2q_kernel<<<ROWS, 256>>>(ctx, ques, wsim, q2, xs, rowmax);
    bsoftmax_q2c_kernel<<<Bz, 256>>>(ctx, rowmax, q2c);
    fillx4_kernel<<<ROWS, 256>>>(ctx, q2c, xs);
    extract_w_kernel<<<4, 256>>>(Wb, w01, w10, w11);

    // weight prep (transpose + hi/lo split, B-layout hi,hi,lo)
    prep_bsplit<<<dim3(16, 32), dim3(32, 8)>>>(W1s, 512, w1s, 1024, 1024, 512);
    prep_bsplit<<<dim3(16, 32), dim3(32, 8)>>>(W1e, 512, w1e, 1024, 1024, 512);
    prep_bsplit<<<dim3(32, 16), dim3(32, 8)>>>(W2s, 1024, w2s, 512, 512, 1024);
    prep_bsplit<<<dim3(32, 16), dim3(32, 8)>>>(W2e, 1024, w2e, 512, 512, 1024);
    for (int c = 0; c < 3; c++)
        prep_bsplit<<<dim3(32, 32), dim3(32, 8)>>>(Wb + (size_t)c*1025, 3075,
                                                   wbt + (size_t)c*1024*KS, 1024, 1024, 1024);

    long long zero = 0;
    // FFW start: h1 = relu(x@W1s + b1s)  (A-layout out: hi,lo,hi)
    mma_gemm<<<dim3(4, 64, 1), 256>>>(xs, KX, zero, zero, w1s, KX, zero, zero,
        96, 1, 0, h1s, KH, 512, 1024, 1, b1s, 1, nullptr, 0, zero, zero, nullptr, nullptr);
    // start = h1@W2s + b2s  (A-layout hi,lo,hi)
    mma_gemm<<<dim3(8, 64, 1), 256>>>(h1s, KH, zero, zero, w2s, KH, zero, zero,
        48, 1, 0, s1s, KS, 1024, 2048, 1, b2s, 0, nullptr, 0, zero, zero, nullptr, nullptr);
    // FFW end
    mma_gemm<<<dim3(4, 64, 1), 256>>>(xs, KX, zero, zero, w1e, KX, zero, zero,
        96, 1, 0, h1s, KH, 512, 1024, 1, b1e, 1, nullptr, 0, zero, zero, nullptr, nullptr);
    // end = h1@W2e + b2e  (B-layout hi,hi,lo)
    mma_gemm<<<dim3(8, 64, 1), 256>>>(h1s, KH, zero, zero, w2e, KH, zero, zero,
        48, 1, 0, e1s, KS, 1024, 2048, 0, b2e, 0, nullptr, 0, zero, zero, nullptr, nullptr);

    // rank-1 terms
    uv_kernel<<<ROWS, 256>>>(s1s, e1s, w01, w10, w11, u, v);

    // Biaffine stage 1: T[z=b*3+c] = start_b @ wbt_c^T  (A-layout out)
    mma_gemm<<<dim3(8, 4, 48), 256>>>(
        s1s, KS, (long long)LC*KS, zero,
        wbt, KS, zero, (long long)1024*KS,
        96, 3,
        0, Ts, KS, 1024, 2048, 1, nullptr, 0,
        nullptr, 0, (long long)3*LC*KS, (long long)LC*KS, nullptr, nullptr);

    // Biaffine stage 2: out[b,:,:,c] = T[z] @ end_b^T + u[z][x] + v[z][y]
    mma_gemm<<<dim3(4, 4, 48), 256>>>(
        Ts, KS, (long long)3*LC*KS, (long long)LC*KS,
        e1s, KS, (long long)LC*KS, zero,
        96, 3,
        1, nullptr, 0, 0, 0, 0, nullptr, 0,
        out, LC*3, (long long)LC*LC*3, 1ll, u, v);
}

// round 6
// speedup vs baseline: 1.5730x; 1.1822x over previous
#include <cuda_runtime.h>
#include <cuda_bf16.h>
#include <cstdint>
#include <math.h>

// Problem constants
#define Bz   16
#define LC   512
#define LQ   64
#define Hd   256
#define ROWS (Bz*LC)     // 8192

// Split-K padded strides (K'' = 3 * K), all in bf16 elements
#define KX   3072        // x'' / W1''  (K=1024)
#define KH   1536        // h1'' / W2'' (K=512)
#define KS   3072        // s1''/e1''/T''/wbt (K=1024, exact)

// -------------------- device scratch (zero-init .bss) --------------------
__device__ float g_q2[Bz*LQ];
__device__ float g_rowmax[ROWS];
__device__ float g_q2c[Bz*Hd];
__device__ float g_w01[3*1024];
__device__ float g_w10[3*1024];
__device__ float g_w11[3];
__device__ float g_u[48*512];
__device__ float g_v[48*512];
__device__ __align__(16) __nv_bfloat16 g_xs [(size_t)ROWS*KX];
__device__ __align__(16) __nv_bfloat16 g_h1s[(size_t)ROWS*KH];
__device__ __align__(16) __nv_bfloat16 g_s1s[(size_t)ROWS*KS];
__device__ __align__(16) __nv_bfloat16 g_e1s[(size_t)ROWS*KS];
__device__ __align__(16) __nv_bfloat16 g_Ts [(size_t)48*LC*KS];
__device__ __align__(16) __nv_bfloat16 g_w1s[(size_t)512*KX];
__device__ __align__(16) __nv_bfloat16 g_w1e[(size_t)512*KX];
__device__ __align__(16) __nv_bfloat16 g_w2s[(size_t)1024*KH];
__device__ __align__(16) __nv_bfloat16 g_w2e[(size_t)1024*KH];
__device__ __align__(16) __nv_bfloat16 g_wbt[(size_t)3*1024*KS];

// -------------------- helpers --------------------
__device__ __forceinline__ uint32_t smem_u32(const void* p) {
    uint32_t a;
    asm("{ .reg .u64 t; cvta.to.shared.u64 t, %1; cvt.u32.u64 %0, t; }" : "=r"(a) : "l"(p));
    return a;
}
__device__ __forceinline__ void cp16(uint32_t saddr, const void* g) {
    asm volatile("cp.async.ca.shared.global [%0], [%1], 16;" :: "r"(saddr), "l"(g) : "memory");
}
__device__ __forceinline__ void cp_commit() { asm volatile("cp.async.commit_group;" ::: "memory"); }
__device__ __forceinline__ void cp_wait0()  { asm volatile("cp.async.wait_group 0;" ::: "memory"); }
__device__ __forceinline__ void cp_wait1()  { asm volatile("cp.async.wait_group 1;" ::: "memory"); }

__device__ __forceinline__ void split2(float v, __nv_bfloat16& hi, __nv_bfloat16& lo) {
    hi = __float2bfloat16(v);
    lo = __float2bfloat16(v - __bfloat162float(hi));
}
__device__ __forceinline__ unsigned short b16bits(__nv_bfloat16 h) {
    return *reinterpret_cast<unsigned short*>(&h);
}
__device__ __forceinline__ void ldm4(uint32_t* r, uint32_t saddr) {
    asm volatile("ldmatrix.sync.aligned.m8n8.x4.shared.b16 {%0,%1,%2,%3}, [%4];"
                 : "=r"(r[0]), "=r"(r[1]), "=r"(r[2]), "=r"(r[3]) : "r"(saddr));
}
__device__ __forceinline__ void mma16816(float* c, const uint32_t* a, const uint32_t* b) {
    asm volatile(
        "mma.sync.aligned.m16n8k16.row.col.f32.bf16.bf16.f32 "
        "{%0,%1,%2,%3}, {%4,%5,%6,%7}, {%8,%9}, {%0,%1,%2,%3};"
        : "+f"(c[0]), "+f"(c[1]), "+f"(c[2]), "+f"(c[3])
        : "r"(a[0]), "r"(a[1]), "r"(a[2]), "r"(a[3]), "r"(b[0]), "r"(b[1]));
}

// -------------------- attention front-end --------------------
__device__ __forceinline__ void xsplit_store(__nv_bfloat16* xr, int col, float v) {
    __nv_bfloat16 hi, lo; split2(v, hi, lo);
    xr[col] = hi; xr[col + 1024] = lo; xr[col + 2048] = hi;   // A-layout: hi, lo, hi
}

__global__ void qdot_kernel(const float* __restrict__ ques, const float* __restrict__ wsim,
                            float* __restrict__ q2) {
    int b = blockIdx.x, j = blockIdx.y, l = threadIdx.x;
    const float* q = ques + ((size_t)(b*LQ + j))*Hd;
    float s = 0.f;
    #pragma unroll
    for (int u = 0; u < Hd/32; u++) s += q[l + u*32] * wsim[Hd + l + u*32];
    #pragma unroll
    for (int o = 16; o > 0; o >>= 1) s += __shfl_down_sync(0xffffffffu, s, o);
    if (l == 0) q2[b*LQ + j] = s;
}

__global__ void sim_softmax_c2q_kernel(const float* __restrict__ ctx,
                                       const float* __restrict__ ques,
                                       const float* __restrict__ wsim,
                                       const float* __restrict__ q2,
                                       __nv_bfloat16* __restrict__ xs,
                                       float* __restrict__ rowmax) {
    int row = blockIdx.x, b = row >> 9;
    int t = threadIdx.x, w = t >> 5, l = t & 31;
    __shared__ float ctxs[Hd], cw3[Hd], simv[LQ], sred[8];
    __shared__ float c1s;

    const float* crow = ctx + (size_t)row * Hd;
    float cv = crow[t];
    ctxs[t] = cv;
    cw3[t]  = cv * wsim[2*Hd + t];

    float v = cv * wsim[t];
    #pragma unroll
    for (int o = 16; o > 0; o >>= 1) v += __shfl_down_sync(0xffffffffu, v, o);
    if (l == 0) sred[w] = v;
    __syncthreads();
    if (t == 0) { float s = 0.f; for (int u = 0; u < 8; u++) s += sred[u]; c1s = s; }
    __syncthreads();

    const float* qb = ques + (size_t)b * LQ * Hd;
    #pragma unroll
    for (int jj = 0; jj < 8; jj++) {
        int j = w * 8 + jj;
        const float* q = qb + (size_t)j * Hd;
        float s = 0.f;
        #pragma unroll
        for (int u = 0; u < Hd/32; u++) s += cw3[l + u*32] * q[l + u*32];
        #pragma unroll
        for (int o = 16; o > 0; o >>= 1) s += __shfl_down_sync(0xffffffffu, s, o);
        if (l == 0) simv[j] = c1s + q2[b*LQ + j] + s;
    }
    __syncthreads();

    if (t < 32) {
        float s0 = simv[t], s1v = simv[t + 32];
        float m = fmaxf(s0, s1v);
        #pragma unroll
        for (int o = 16; o > 0; o >>= 1) m = fmaxf(m, __shfl_xor_sync(0xffffffffu, m, o));
        if (t == 0) rowmax[row] = m;
        float e0 = expf(s0 - m), e1v = expf(s1v - m);
        float sum = e0 + e1v;
        #pragma unroll
        for (int o = 16; o > 0; o >>= 1) sum += __shfl_xor_sync(0xffffffffu, sum, o);
        float inv = 1.f / sum;
        simv[t] = e0 * inv; simv[t + 32] = e1v * inv;
    }
    __syncthreads();

    float acc = 0.f;
    #pragma unroll 8
    for (int j = 0; j < LQ; j++) acc += simv[j] * qb[(size_t)j*Hd + t];

    __nv_bfloat16* xr = xs + (size_t)row * KX;
    xsplit_store(xr, t,        ctxs[t]);
    xsplit_store(xr, Hd + t,   acc);
    xsplit_store(xr, 2*Hd + t, ctxs[t] * acc);
}

__global__ void bsoftmax_q2c_kernel(const float* __restrict__ ctx,
                                    const float* __restrict__ rowmax,
                                    float* __restrict__ q2c) {
    int b = blockIdx.x, t = threadIdx.x;
    __shared__ float w[LC]; __shared__ float sred[8]; __shared__ float mshared, sshared;
    w[t] = rowmax[b*LC + t]; w[t + 256] = rowmax[b*LC + t + 256];
    __syncthreads();
    float m = fmaxf(w[t], w[t + 256]);
    #pragma unroll
    for (int o = 16; o > 0; o >>= 1) m = fmaxf(m, __shfl_xor_sync(0xffffffffu, m, o));
    if ((t & 31) == 0) sred[t >> 5] = m;
    __syncthreads();
    if (t == 0) { float mm = sred[0]; for (int u = 1; u < 8; u++) mm = fmaxf(mm, sred[u]); mshared = mm; }
    __syncthreads();
    m = mshared;
    float e0 = expf(w[t] - m), e1v = expf(w[t + 256] - m);
    float s = e0 + e1v;
    #pragma unroll
    for (int o = 16; o > 0; o >>= 1) s += __shfl_xor_sync(0xffffffffu, s, o);
    if ((t & 31) == 0) sred[t >> 5] = s;
    __syncthreads();
    if (t == 0) { float ss = 0.f; for (int u = 0; u < 8; u++) ss += sred[u]; sshared = ss; }
    __syncthreads();
    float inv = 1.f / sshared;
    w[t] = e0 * inv; w[t + 256] = e1v * inv;
    __syncthreads();
    float acc = 0.f;
    const float* cb = ctx + (size_t)b * LC * Hd;
    for (int i = 0; i < LC; i++) acc += w[i] * cb[(size_t)i*Hd + t];
    q2c[b*Hd + t] = acc;
}

__global__ void fillx4_kernel(const float* __restrict__ ctx,
                              const float* __restrict__ q2c,
                              __nv_bfloat16* __restrict__ xs) {
    int row = blockIdx.x, t = threadIdx.x, b = row >> 9;
    float c = ctx[(size_t)row*Hd + t];
    xsplit_store(xs + (size_t)row*KX, 3*Hd + t, c * q2c[b*Hd + t]);
}

// extract rank-1 parts of Wb: w01[c][i]=Wb[i,c,1024], w10[c][j]=Wb[1024,c,j], w11[c]
__global__ void extract_w_kernel(const float* __restrict__ Wb,
                                 float* __restrict__ w01, float* __restrict__ w10,
                                 float* __restrict__ w11) {
    int i = blockIdx.x*256 + threadIdx.x;   // 0..1023
    #pragma unroll
    for (int c = 0; c < 3; c++) {
        w01[c*1024 + i] = Wb[(size_t)i*3075 + c*1025 + 1024];
        w10[c*1024 + i] = Wb[(size_t)1024*3075 + c*1025 + i];
    }
    if (i < 3) w11[i] = Wb[(size_t)1024*3075 + (size_t)i*1025 + 1024];
}

// u[z=b*3+c][x] = start[b,x]·w01[c] + w11[c] ; v[z][y] = end[b,y]·w10[c]
__global__ void uv_kernel(const __nv_bfloat16* __restrict__ s1s,
                          const __nv_bfloat16* __restrict__ e1s,
                          const float* __restrict__ w01, const float* __restrict__ w10,
                          const float* __restrict__ w11,
                          float* __restrict__ u, float* __restrict__ v) {
    int row = blockIdx.x, t = threadIdx.x, w = t >> 5, l = t & 31;
    int b = row >> 9, x = row & 511;
    const __nv_bfloat16* sr = s1s + (size_t)row*KS;
    const __nv_bfloat16* er = e1s + (size_t)row*KS;
    float a[6] = {0,0,0,0,0,0};
    for (int i = t; i < 1024; i += 256) {
        float sv = __bfloat162float(sr[i]) + __bfloat162float(sr[i + 1024]);  // A-layout: hi,lo,hi
        float ev = __bfloat162float(er[i]) + __bfloat162float(er[i + 2048]);  // B-layout: hi,hi,lo
        #pragma unroll
        for (int c = 0; c < 3; c++) {
            a[c]     += sv * w01[c*1024 + i];
            a[3 + c] += ev * w10[c*1024 + i];
        }
    }
    __shared__ float red[6][8];
    #pragma unroll
    for (int q = 0; q < 6; q++) {
        float s = a[q];
        #pragma unroll
        for (int o = 16; o > 0; o >>= 1) s += __shfl_down_sync(0xffffffffu, s, o);
        if (l == 0) red[q][w] = s;
    }
    __syncthreads();
    if (t < 6) {
        float s = 0.f;
        #pragma unroll
        for (int k = 0; k < 8; k++) s += red[t][k];
        if (t < 3) u[(b*3 + t)*512 + x] = s + w11[t];
        else       v[(b*3 + (t - 3))*512 + x] = s;
    }
}

// Transpose + split weights into B-layout [N rows x 3*Kpad]: blocks (hi, hi, lo)
__global__ void prep_bsplit(const float* __restrict__ src, int srcLd,
                            __nv_bfloat16* __restrict__ dst,
                            int Kreal, int Kpad, int Nrows) {
    __shared__ float tile[32][33];
    int k0 = blockIdx.y*32, n0 = blockIdx.x*32;
    int tx = threadIdx.x, ty = threadIdx.y;
    #pragma unroll
    for (int i = 0; i < 32; i += 8) {
        int k = k0 + ty + i, n = n0 + tx;
        tile[ty + i][tx] = (k < Kreal && n < Nrows) ? src[(size_t)k*srcLd + n] : 0.f;
    }
    __syncthreads();
    int ldd = 3*Kpad;
    #pragma unroll
    for (int i = 0; i < 32; i += 8) {
        int n = n0 + ty + i, k = k0 + tx;
        if (n < Nrows) {
            __nv_bfloat16 hi, lo; split2(tile[tx][ty + i], hi, lo);
            size_t base = (size_t)n*ldd + k;
            dst[base] = hi; dst[base + Kpad] = hi; dst[base + 2*Kpad] = lo;
        }
    }
}

// -------------------- warp-mma GEMM (bf16, fp32 acc, ldmatrix, 3-stage) ------
// D = A @ B^T ; A [M,K''] K-major, B [N,K''] K-major. All dims exact multiples
// of the 128x128x32 block tile -> no bounds checks. 8 warps, 64x32 warp tile.
// ldmatrix fragment loads batched (B per chunk, A per kstep) before MMA blocks.
#define LDR 40   // smem row stride in bf16 (80 bytes) -> conflict-free
#define STAGES 3
#define STG_ELEMS (128*LDR)               // per-stage elems per matrix
#define SMEM_BYTES (STAGES*2*STG_ELEMS*2) // 61440

__device__ __forceinline__ void store_pair_split(
    __nv_bfloat16* p, int n, float v0, float v1,
    int blk1, int blk2, int b1lo, const float* bias, int relu)
{
    if (bias) { v0 += bias[n]; v1 += bias[n + 1]; }
    if (relu) { v0 = fmaxf(v0, 0.f); v1 = fmaxf(v1, 0.f); }
    __nv_bfloat16 h0, l0, h1, l1;
    split2(v0, h0, l0); split2(v1, h1, l1);
    uint32_t H = (uint32_t)b16bits(h0) | ((uint32_t)b16bits(h1) << 16);
    uint32_t L = (uint32_t)b16bits(l0) | ((uint32_t)b16bits(l1) << 16);
    *reinterpret_cast<uint32_t*>(p + n) = H;
    *reinterpret_cast<uint32_t*>(p + blk1 + n) = b1lo ? L : H;
    *reinterpret_cast<uint32_t*>(p + blk2 + n) = b1lo ? H : L;
}

__global__ __launch_bounds__(256, 2)
void mma_gemm(const __nv_bfloat16* __restrict__ A, int lda, long long aZb, long long aZc,
              const __nv_bfloat16* __restrict__ B, int ldb, long long bZb, long long bZc,
              int nch, int zdiv, int mode,
              __nv_bfloat16* outS, int ldo, int blk1, int blk2, int b1lo,
              const float* bias, int relu,
              float* outF, int ldcM, long long cZb, long long cZc,
              const float* uArr, const float* vArr)
{
    extern __shared__ __nv_bfloat16 smem_dyn[];
    const int LDR2 = LDR*2;

    int tid = threadIdx.x;
    int z = blockIdx.z, zb = z / zdiv, zc = z - zb * zdiv;
    const __nv_bfloat16* Ab = A + (size_t)zb*aZb + (size_t)zc*aZc + (size_t)(blockIdx.y*128)*lda;
    const __nv_bfloat16* Bb = B + (size_t)zb*bZb + (size_t)zc*bZc + (size_t)(blockIdx.x*128)*ldb;
    int m0 = blockIdx.y * 128, n0 = blockIdx.x * 128;

    int lane = tid & 31, wid = tid >> 5;
    int wm = (wid & 1) * 64, wn = (wid >> 1) * 32;
    int ar = lane >> 2, ac = (lane & 3) * 2;

    int lrow = tid >> 2, lseg = tid & 3;               // loader: 4 threads/row
    uint32_t sAu = smem_u32(smem_dyn);
    uint32_t sBu = sAu + STAGES*STG_ELEMS*2;
    uint32_t lso = lrow*LDR2 + lseg*16;

    // ldmatrix per-thread byte offsets (within a stage)
    uint32_t aoff = (uint32_t)(wm + (lane & 15))*LDR2 + (lane >> 4)*16;
    uint32_t boff = (uint32_t)(wn + (lane & 7))*LDR2 + (lane >> 3)*16;

    float acc[4][4][4];
    #pragma unroll
    for (int i = 0; i < 4; i++)
        #pragma unroll
        for (int j = 0; j < 4; j++)
            #pragma unroll
            for (int q = 0; q < 4; q++) acc[i][j][q] = 0.f;

    // prologue: load chunks 0 and 1 into slots 0 and 1
    #pragma unroll
    for (int p = 0; p < 2; p++) {
        int k0 = p * 32;
        const __nv_bfloat16* ga = Ab + (size_t)lrow*lda + k0 + lseg*8;
        const __nv_bfloat16* gb = Bb + (size_t)lrow*ldb + k0 + lseg*8;
        uint32_t da = sAu + p*(STG_ELEMS*2), db = sBu + p*(STG_ELEMS*2);
        cp16(da + lso, ga);            cp16(db + lso, gb);
        cp16(da + lso + 64*LDR2, ga + (size_t)64*lda);
        cp16(db + lso + 64*LDR2, gb + (size_t)64*ldb);
        cp_commit();
    }

    int slot = 0, lslot = 2;
    for (int c = 0; c < nch; c++) {
        if (c >= nch - 1) cp_wait0(); else cp_wait1();
        __syncthreads();

        if (c + 2 < nch) {
            int k0 = (c + 2) * 32;
            const __nv_bfloat16* ga = Ab + (size_t)lrow*lda + k0 + lseg*8;
            const __nv_bfloat16* gb = Bb + (size_t)lrow*ldb + k0 + lseg*8;
            uint32_t da = sAu + lslot*(STG_ELEMS*2), db = sBu + lslot*(STG_ELEMS*2);
            cp16(da + lso, ga);            cp16(db + lso, gb);
            cp16(da + lso + 64*LDR2, ga + (size_t)64*lda);
            cp16(db + lso + 64*LDR2, gb + (size_t)64*ldb);
            cp_commit();
            lslot++; if (lslot == STAGES) lslot = 0;
        }

        uint32_t sa = sAu + slot*(STG_ELEMS*2);
        uint32_t sbb = sBu + slot*(STG_ELEMS*2);
        slot++; if (slot == STAGES) slot = 0;

        // B fragments for the whole chunk (both ksteps): 4 LDSM
        uint32_t bf[4][4];
        #pragma unroll
        for (int nt = 0; nt < 4; nt++) ldm4(bf[nt], sbb + boff + nt*(8*LDR2));

        #pragma unroll
        for (int ks = 0; ks < 2; ks++) {
            // A fragments for this kstep: 4 LDSM batched
            uint32_t af[4][4];
            #pragma unroll
            for (int mt = 0; mt < 4; mt++)
                ldm4(af[mt], sa + aoff + mt*(16*LDR2) + ks*32);
            #pragma unroll
            for (int mt = 0; mt < 4; mt++)
                #pragma unroll
                for (int nt = 0; nt < 4; nt++)
                    mma16816(acc[mt][nt], af[mt], &bf[nt][ks*2]);
        }
    }
    __syncthreads();

    // -------- epilogue --------
    if (mode == 0) {
        __nv_bfloat16* base = outS + (size_t)zb*cZb + (size_t)zc*cZc;
        #pragma unroll
        for (int mt = 0; mt < 4; mt++) {
            int m = m0 + wm + mt*16 + ar;
            __nv_bfloat16* p0 = base + (size_t)m*ldo;
            __nv_bfloat16* p1 = p0 + (size_t)8*ldo;
            #pragma unroll
            for (int nt = 0; nt < 4; nt++) {
                int n = n0 + wn + nt*8 + ac;
                store_pair_split(p0, n, acc[mt][nt][0], acc[mt][nt][1], blk1, blk2, b1lo, bias, relu);
                store_pair_split(p1, n, acc[mt][nt][2], acc[mt][nt][3], blk1, blk2, b1lo, bias, relu);
            }
        }
    } else {
        float* base = outF + (size_t)zb*cZb + (size_t)zc*cZc;
        const float* uz = uArr + (size_t)z*512;
        const float* vz = vArr + (size_t)z*512;
        #pragma unroll
        for (int mt = 0; mt < 4; mt++) {
            int m = m0 + wm + mt*16 + ar;
            float u0 = uz[m], u1 = uz[m + 8];
            float* p0 = base + (size_t)m*ldcM;
            float* p1 = p0 + (size_t)8*ldcM;
            #pragma unroll
            for (int nt = 0; nt < 4; nt++) {
                int n = n0 + wn + nt*8 + ac;
                float vn0 = vz[n], vn1 = vz[n + 1];
                p0[(size_t)n*3]     = acc[mt][nt][0] + u0 + vn0;
                p0[(size_t)(n+1)*3] = acc[mt][nt][1] + u0 + vn1;
                p1[(size_t)n*3]     = acc[mt][nt][2] + u1 + vn0;
                p1[(size_t)(n+1)*3] = acc[mt][nt][3] + u1 + vn1;
            }
        }
    }
}

// -------------------- launcher --------------------
extern "C" void kernel_launch(void* const* d_in, const int* in_sizes, int n_in,
                              void* d_out, int out_size) {
    const float* ctx  = (const float*)d_in[0];
    const float* ques = (const float*)d_in[1];
    const float* wsim = (const float*)d_in[2];
    const float* W1s  = (const float*)d_in[3];
    const float* b1s  = (const float*)d_in[4];
    const float* W2s  = (const float*)d_in[5];
    const float* b2s  = (const float*)d_in[6];
    const float* W1e  = (const float*)d_in[7];
    const float* b1e  = (const float*)d_in[8];
    const float* W2e  = (const float*)d_in[9];
    const float* b2e  = (const float*)d_in[10];
    const float* Wb   = (const float*)d_in[11];
    float* out = (float*)d_out;

    float *q2, *rowmax, *q2c, *w01, *w10, *w11, *u, *v;
    __nv_bfloat16 *xs, *h1s, *s1s, *e1s, *Ts, *w1s, *w1e, *w2s, *w2e, *wbt;
    cudaGetSymbolAddress((void**)&q2, g_q2);
    cudaGetSymbolAddress((void**)&rowmax, g_rowmax);
    cudaGetSymbolAddress((void**)&q2c, g_q2c);
    cudaGetSymbolAddress((void**)&w01, g_w01);
    cudaGetSymbolAddress((void**)&w10, g_w10);
    cudaGetSymbolAddress((void**)&w11, g_w11);
    cudaGetSymbolAddress((void**)&u, g_u);
    cudaGetSymbolAddress((void**)&v, g_v);
    cudaGetSymbolAddress((void**)&xs, g_xs);
    cudaGetSymbolAddress((void**)&h1s, g_h1s);
    cudaGetSymbolAddress((void**)&s1s, g_s1s);
    cudaGetSymbolAddress((void**)&e1s, g_e1s);
    cudaGetSymbolAddress((void**)&Ts, g_Ts);
    cudaGetSymbolAddress((void**)&w1s, g_w1s);
    cudaGetSymbolAddress((void**)&w1e, g_w1e);
    cudaGetSymbolAddress((void**)&w2s, g_w2s);
    cudaGetSymbolAddress((void**)&w2e, g_w2e);
    cudaGetSymbolAddress((void**)&wbt, g_wbt);

    cudaFuncSetAttribute(mma_gemm, cudaFuncAttributeMaxDynamicSharedMemorySize, SMEM_BYTES);

    // front-end
    qdot_kernel<<<dim3(Bz, LQ), 32>>>(ques, wsim, q2);
    sim_softmax_c2q_kernel<<<ROWS, 256>>>(ctx, ques, wsim, q2, xs, rowmax);
    bsoftmax_q2c_kernel<<<Bz, 256>>>(ctx, rowmax, q2c);
    fillx4_kernel<<<ROWS, 256>>>(ctx, q2c, xs);
    extract_w_kernel<<<4, 256>>>(Wb, w01, w10, w11);

    // weight prep (transpose + hi/lo split, B-layout hi,hi,lo)
    prep_bsplit<<<dim3(16, 32), dim3(32, 8)>>>(W1s, 512, w1s, 1024, 1024, 512);
    prep_bsplit<<<dim3(16, 32), dim3(32, 8)>>>(W1e, 512, w1e, 1024, 1024, 512);
    prep_bsplit<<<dim3(32, 16), dim3(32, 8)>>>(W2s, 1024, w2s, 512, 512, 1024);
    prep_bsplit<<<dim3(32, 16), dim3(32, 8)>>>(W2e, 1024, w2e, 512, 512, 1024);
    for (int c = 0; c < 3; c++)
        prep_bsplit<<<dim3(32, 32), dim3(32, 8)>>>(Wb + (size_t)c*1025, 3075,
                                                   wbt + (size_t)c*1024*KS, 1024, 1024, 1024);

    long long zero = 0;
    // FFW start: h1 = relu(x@W1s + b1s)  (A-layout out: hi,lo,hi)
    mma_gemm<<<dim3(4, 64, 1), 256, SMEM_BYTES>>>(xs, KX, zero, zero, w1s, KX, zero, zero,
        96, 1, 0, h1s, KH, 512, 1024, 1, b1s, 1, nullptr, 0, zero, zero, nullptr, nullptr);
    // start = h1@W2s + b2s  (A-layout hi,lo,hi)
    mma_gemm<<<dim3(8, 64, 1), 256, SMEM_BYTES>>>(h1s, KH, zero, zero, w2s, KH, zero, zero,
        48, 1, 0, s1s, KS, 1024, 2048, 1, b2s, 0, nullptr, 0, zero, zero, nullptr, nullptr);
    // FFW end
    mma_gemm<<<dim3(4, 64, 1), 256, SMEM_BYTES>>>(xs, KX, zero, zero, w1e, KX, zero, zero,
        96, 1, 0, h1s, KH, 512, 1024, 1, b1e, 1, nullptr, 0, zero, zero, nullptr, nullptr);
    // end = h1@W2e + b2e  (B-layout hi,hi,lo)
    mma_gemm<<<dim3(8, 64, 1), 256, SMEM_BYTES>>>(h1s, KH, zero, zero, w2e, KH, zero, zero,
        48, 1, 0, e1s, KS, 1024, 2048, 0, b2e, 0, nullptr, 0, zero, zero, nullptr, nullptr);

    // rank-1 terms
    uv_kernel<<<ROWS, 256>>>(s1s, e1s, w01, w10, w11, u, v);

    // Biaffine stage 1: T[z=b*3+c] = start_b @ wbt_c^T  (A-layout out)
    mma_gemm<<<dim3(8, 4, 48), 256, SMEM_BYTES>>>(
        s1s, KS, (long long)LC*KS, zero,
        wbt, KS, zero, (long long)1024*KS,
        96, 3,
        0, Ts, KS, 1024, 2048, 1, nullptr, 0,
        nullptr, 0, (long long)3*LC*KS, (long long)LC*KS, nullptr, nullptr);

    // Biaffine stage 2: out[b,:,:,c] = T[z] @ end_b^T + u[z][x] + v[z][y]
    mma_gemm<<<dim3(4, 4, 48), 256, SMEM_BYTES>>>(
        Ts, KS, (long long)3*LC*KS, (long long)LC*KS,
        e1s, KS, (long long)LC*KS, zero,
        96, 3,
        1, nullptr, 0, 0, 0, 0, nullptr, 0,
        out, LC*3, (long long)LC*LC*3, 1ll, u, v);
}